// round 12
// baseline (speedup 1.0000x reference)
#include <cuda_runtime.h>

#define NGRAPH 256
#define M      512
#define KNN    6
#define C      32
#define FINF   3.402823466e38f
#define ROWF   36            // padded U row (floats): 144B, 16B aligned
#define ROWB   144
#define P1N    128           // KNN phase-1 sample size
#define CAP    96            // per-thread u16 candidate buffer capacity
#define NPACK  5640          // packed weights (floats)

typedef unsigned long long ull;

__device__ int   g_idxT[NGRAPH * KNN * M];   // [graph][k][node], byte offsets (idx*ROWB)
__device__ __align__(16) float g_pack[NPACK];

// packed-weight float offsets
#define O_W1A 0
#define O_B1A 128
#define O_W2A 160
#define O_B2A 1184
#define O_W1B 1216
#define O_B1B 2240
#define O_W2B 2272
#define O_B2B 3296
#define O_W1C 3328
#define O_B1C 4352
#define O_W2C 4384
#define O_B2C 5408
#define O_WR  5440
#define O_BR  5632

// single consolidated constant block (separate LDC port, parallel to L1)
__constant__ __align__(16) float cALL[NPACK];
#define W1A ((const ulonglong2*)(cALL + O_W1A))
#define W2A ((const ulonglong2*)(cALL + O_W2A))
#define W1B ((const ulonglong2*)(cALL + O_W1B))
#define W2B ((const ulonglong2*)(cALL + O_W2B))
#define W1C ((const ulonglong2*)(cALL + O_W1C))
#define W2C ((const ulonglong2*)(cALL + O_W2C))
#define B1A (cALL + O_B1A)
#define B2A (cALL + O_B2A)
#define B1B (cALL + O_B1B)
#define B2B (cALL + O_B2B)
#define B1C (cALL + O_B1C)
#define B2C (cALL + O_B2C)
#define WR  (cALL + O_WR)
#define BR  (cALL + O_BR)

static __device__ __forceinline__ ull pk2(float lo, float hi) {
    ull d; asm("mov.b64 %0, {%1, %2};" : "=l"(d) : "f"(lo), "f"(hi)); return d;
}
static __device__ __forceinline__ float2 upk2(ull v) {
    float2 r; asm("mov.b64 {%0, %1}, %2;" : "=f"(r.x), "=f"(r.y) : "l"(v)); return r;
}
static __device__ __forceinline__ ull ffma2(ull a, ull b, ull c) {
    ull d; asm("fma.rn.f32x2 %0, %1, %2, %3;" : "=l"(d) : "l"(a), "l"(b), "l"(c)); return d;
}
static __device__ __forceinline__ float4 fmax4(float4 a, float4 b) {
    return make_float4(fmaxf(a.x, b.x), fmaxf(a.y, b.y),
                       fmaxf(a.z, b.z), fmaxf(a.w, b.w));
}
static __device__ __forceinline__ void sts16_if(unsigned addr, unsigned short v, int pred) {
    asm volatile("{\n\t.reg .pred p;\n\tsetp.ne.s32 p, %2, 0;\n\t"
                 "@p st.shared.u16 [%0], %1;\n\t}"
                 :: "r"(addr), "h"(v), "r"(pred));
}
static __device__ __forceinline__ float d2f(float4 a, float4 j) {
    float dot = fmaf(a.x, j.x, fmaf(a.y, j.y, a.z * j.z));
    return fmaf(-2.0f, dot, a.w + j.w);       // exact reference formula
}

__device__ __forceinline__ void kins(float (&bd)[KNN], int (&bi)[KNN],
                                     float xd, int xi)
{
#pragma unroll
    for (int k = 0; k < KNN; k++) {
        bool  p  = xd < bd[k];                // strict: stable (ties keep earlier j)
        float td = bd[k];
        int   ti = bi[k];
        bd[k] = p ? xd : bd[k];
        bi[k] = p ? xi : bi[k];
        xd    = p ? td : xd;
        xi    = p ? ti : xi;
    }
}

// ============================================================================
// Kernel 0: parallel weight pack (one float per thread)
// ============================================================================
__global__ void pack_weights(
    const float* __restrict__ W1a, const float* __restrict__ b1a,
    const float* __restrict__ W2a, const float* __restrict__ b2a,
    const float* __restrict__ W1b, const float* __restrict__ b1b,
    const float* __restrict__ W2b, const float* __restrict__ b2b,
    const float* __restrict__ W1c, const float* __restrict__ b1c,
    const float* __restrict__ W2c, const float* __restrict__ b2c,
    const float* __restrict__ Wr,  const float* __restrict__ br)
{
    int i = blockIdx.x * blockDim.x + threadIdx.x;
    if (i >= NPACK) return;
    float v = 0.f;
    if      (i < O_B1A) v = W1a[i - O_W1A];
    else if (i < O_W2A) v = b1a[i - O_B1A];
    else if (i < O_B2A) v = W2a[i - O_W2A];
    else if (i < O_W1B) v = b2a[i - O_B2A];
    else if (i < O_B1B) v = W1b[i - O_W1B];
    else if (i < O_W2B) v = b1b[i - O_B1B];
    else if (i < O_B2B) v = W2b[i - O_W2B];
    else if (i < O_W1C) v = b2b[i - O_B2B];
    else if (i < O_B1C) v = W1c[i - O_W1C];
    else if (i < O_W2C) v = b1c[i - O_B1C];
    else if (i < O_B2C) v = W2c[i - O_W2C];
    else if (i < O_WR)  v = b2c[i - O_B2C];
    else if (i < O_BR)  v = Wr[i - O_WR];
    else if (i < O_BR + 6) v = br[i - O_BR];
    g_pack[i] = v;
}

// ============================================================================
// Kernel 1: 3-phase KNN. 2 blocks/graph, 256 threads, 1 node/thread.
// ============================================================================
struct __align__(16) SmemK {
    float4 pos4s[M];                  //  8 KB
    unsigned short buf[256 * CAP];    // 48 KB
};

__global__ void __launch_bounds__(256, 4) knn_kernel(const float* __restrict__ pos)
{
    extern __shared__ char smem_raw[];
    SmemK& sk = *reinterpret_cast<SmemK*>(smem_raw);
    const int b    = blockIdx.x >> 1;
    const int half = blockIdx.x & 1;
    const int t    = threadIdx.x;

#pragma unroll
    for (int i = 0; i < 2; i++) {
        int nn = i * 256 + t;
        const float* p = pos + ((size_t)b * M + nn) * 3;
        float px = p[0], py = p[1], pz = p[2];
        sk.pos4s[nn] = make_float4(px, py, pz, px * px + py * py + pz * pz);
    }
    __syncthreads();

    const int n = half * 256 + t;
    const float4 pn = sk.pos4s[n];

    // ---- phase 1: branchless value-only top-6 over first P1N (exact d2) ----
    float v[KNN];
#pragma unroll
    for (int k = 0; k < KNN; k++) v[k] = FINF;
#pragma unroll 2
    for (int j = 0; j < P1N; j++) {
        float a = d2f(pn, sk.pos4s[j]);
#pragma unroll
        for (int k = 0; k < KNN; k++) {
            float lo = fminf(a, v[k]); a = fmaxf(a, v[k]); v[k] = lo;
        }
    }
    const float taup = (v[KNN - 1] - pn.w) + 1e-4f;

    // ---- phase 2: full scan, predicated append ----
    unsigned short* mybuf = sk.buf + t * CAP;
    unsigned bufaddr = (unsigned)__cvta_generic_to_shared(mybuf);
    int cnt = 0;
#pragma unroll 1
    for (int j0 = 0; j0 < M; j0 += 4) {
        float e[4];
#pragma unroll
        for (int u = 0; u < 4; u++) {
            float4 pj = sk.pos4s[j0 + u];
            float dot = fmaf(pn.x, pj.x, fmaf(pn.y, pj.y, pn.z * pj.z));
            e[u] = fmaf(-2.0f, dot, pj.w);
        }
        int basec = cnt < (CAP - 4) ? cnt : (CAP - 4);
#pragma unroll
        for (int u = 0; u < 4; u++) {
            int p = e[u] <= taup;
            sts16_if(bufaddr + 2u * (unsigned)basec, (unsigned short)(j0 + u), p);
            basec += p;
            cnt   += p;
        }
    }
    asm volatile("" ::: "memory");

    // ---- phase 3: exact stable top-6 ----
    float bd[KNN];
    int   bi[KNN];
#pragma unroll
    for (int k = 0; k < KNN; k++) { bd[k] = FINF; bi[k] = 0; }

    if (cnt <= CAP) {
        for (int i = 0; i < cnt; i++) {
            int j = mybuf[i];
            float d = d2f(pn, sk.pos4s[j]);
            if (d < bd[KNN - 1]) kins(bd, bi, d, j);
        }
    } else {
        for (int j = 0; j < M; j++) {       // rare exact fallback
            float d = d2f(pn, sk.pos4s[j]);
            if (d < bd[KNN - 1]) kins(bd, bi, d, j);
        }
    }

    int* dst = g_idxT + (size_t)b * (KNN * M);
#pragma unroll
    for (int k = 0; k < KNN; k++)
        dst[k * M + n] = bi[k] * ROWB;
}

// ============================================================================
// Kernel 2: fused layers; constant weights; a-values live in registers
// across the barrier (no global round-trip).
// ============================================================================
struct __align__(16) SmemL {
    float U[M * ROWF];   // 73728 B
    float red[256];      //  1024 B
};                       // ~75KB -> 2 CTAs/SM

static __device__ __forceinline__ void gather_relu(const char* __restrict__ Up,
                                                   const int* __restrict__ off,
                                                   ull* __restrict__ hp)
{
#pragma unroll
    for (int c4 = 0; c4 < 8; c4++) {
        int byo = c4 * 16;
        float4 m = *(const float4*)(Up + off[0] + byo);
        m = fmax4(m, *(const float4*)(Up + off[1] + byo));
        m = fmax4(m, *(const float4*)(Up + off[2] + byo));
        m = fmax4(m, *(const float4*)(Up + off[3] + byo));
        m = fmax4(m, *(const float4*)(Up + off[4] + byo));
        m = fmax4(m, *(const float4*)(Up + off[5] + byo));
        m.x = fmaxf(m.x, 0.f); m.y = fmaxf(m.y, 0.f);
        m.z = fmaxf(m.z, 0.f); m.w = fmaxf(m.w, 0.f);
        hp[2 * c4]     = pk2(m.x, m.y);
        hp[2 * c4 + 1] = pk2(m.z, m.w);
    }
}

// dual-node 32x32 matvec -> SMEM rows (4-wide packed stores)
#define MV_ROWS(W, BIAS, P0, P1, RELU, D0, D1)                                  \
    {                                                                           \
        ull s0lo = 0, s0hi = 0, s1lo = 0, s1hi = 0;                             \
        _Pragma("unroll")                                                       \
        for (int o = 0; o < 32; o++) {                                          \
            ull a0 = 0, a1 = 0, b0 = 0, b1 = 0;                                 \
            _Pragma("unroll")                                                   \
            for (int q = 0; q < 8; q++) {                                       \
                ulonglong2 w = (W)[o * 8 + q];                                  \
                a0 = ffma2(w.x, (P0)[2 * q],     a0);                           \
                a1 = ffma2(w.y, (P0)[2 * q + 1], a1);                           \
                b0 = ffma2(w.x, (P1)[2 * q],     b0);                           \
                b1 = ffma2(w.y, (P1)[2 * q + 1], b1);                           \
            }                                                                   \
            float2 e0 = upk2(a0), e1 = upk2(a1);                                \
            float2 f0 = upk2(b0), f1 = upk2(b1);                                \
            float v0 = (e0.x + e0.y) + (e1.x + e1.y) + (BIAS)[o];               \
            float v1 = (f0.x + f0.y) + (f1.x + f1.y) + (BIAS)[o];               \
            if (RELU) { v0 = fmaxf(v0, 0.f); v1 = fmaxf(v1, 0.f); }             \
            switch (o & 3) {                                                    \
              case 0: s0lo = pk2(v0, 0.f); s1lo = pk2(v1, 0.f); break;          \
              case 1: { float2 c0 = upk2(s0lo); s0lo = pk2(c0.x, v0);           \
                        float2 c1 = upk2(s1lo); s1lo = pk2(c1.x, v1); } break;  \
              case 2: s0hi = pk2(v0, 0.f); s1hi = pk2(v1, 0.f); break;          \
              default: {                                                        \
                float2 c0 = upk2(s0hi); s0hi = pk2(c0.x, v0);                   \
                float2 c1 = upk2(s1hi); s1hi = pk2(c1.x, v1);                   \
                *(ulonglong2*)((D0) + o - 3) = make_ulonglong2(s0lo, s0hi);     \
                *(ulonglong2*)((D1) + o - 3) = make_ulonglong2(s1lo, s1hi);     \
              } break;                                                          \
            }                                                                   \
        }                                                                       \
    }

// dual-node 32x32 matvec -> packed register arrays (stays live across barrier)
#define MV_REG(W, BIAS, P0, P1, RELU, OP0, OP1)                                 \
    {                                                                           \
        float pv0 = 0.f, pv1 = 0.f;                                            \
        _Pragma("unroll")                                                       \
        for (int o = 0; o < 32; o++) {                                          \
            ull a0 = 0, a1 = 0, b0 = 0, b1 = 0;                                 \
            _Pragma("unroll")                                                   \
            for (int q = 0; q < 8; q++) {                                       \
                ulonglong2 w = (W)[o * 8 + q];                                  \
                a0 = ffma2(w.x, (P0)[2 * q],     a0);                           \
                a1 = ffma2(w.y, (P0)[2 * q + 1], a1);                           \
                b0 = ffma2(w.x, (P1)[2 * q],     b0);                           \
                b1 = ffma2(w.y, (P1)[2 * q + 1], b1);                           \
            }                                                                   \
            float2 e0 = upk2(a0), e1 = upk2(a1);                                \
            float2 f0 = upk2(b0), f1 = upk2(b1);                                \
            float v0 = (e0.x + e0.y) + (e1.x + e1.y) + (BIAS)[o];               \
            float v1 = (f0.x + f0.y) + (f1.x + f1.y) + (BIAS)[o];               \
            if (RELU) { v0 = fmaxf(v0, 0.f); v1 = fmaxf(v1, 0.f); }             \
            if (o & 1) { (OP0)[o >> 1] = pk2(pv0, v0);                          \
                         (OP1)[o >> 1] = pk2(pv1, v1); }                        \
            else       { pv0 = v0; pv1 = v1; }                                  \
        }                                                                       \
    }

__global__ void __launch_bounds__(256, 2) gcn_layers_kernel(
    const float* __restrict__ x, const float* __restrict__ pos,
    float* __restrict__ out)
{
    extern __shared__ char smem_raw[];
    SmemL& sm = *reinterpret_cast<SmemL*>(smem_raw);

    const int b    = blockIdx.x;
    const int t    = threadIdx.x;
    const int lane = t & 31;
    const int wid  = t >> 5;
    const int n0   = t;
    const int n1   = t + 256;

    float* U0 = sm.U + n0 * ROWF;
    float* U1 = sm.U + n1 * ROWF;

    int off0[KNN], off1[KNN];
    {
        const int* it = g_idxT + (size_t)b * (KNN * M);
#pragma unroll
        for (int k = 0; k < KNN; k++) {
            off0[k] = it[k * M + n0];
            off1[k] = it[k * M + n1];
        }
    }

    // ============ layer A: all-register -> U ============
    {
        float x0 = x[(size_t)b * M + n0];
        float x1 = x[(size_t)b * M + n1];
        const float* p0 = pos + ((size_t)b * M + n0) * 3;
        const float* p1 = pos + ((size_t)b * M + n1) * 3;
        ull i0a = pk2(x0, p0[0]), i0b = pk2(p0[1], p0[2]);
        ull i1a = pk2(x1, p1[0]), i1b = pk2(p1[1], p1[2]);

        ull ap0[16], ap1[16];
        float pr0 = 0.f, pr1 = 0.f;
#pragma unroll
        for (int o = 0; o < 32; o++) {
            ulonglong2 w = W1A[o];
            float2 e0 = upk2(ffma2(w.x, i0a, ffma2(w.y, i0b, 0ull)));
            float2 e1 = upk2(ffma2(w.x, i1a, ffma2(w.y, i1b, 0ull)));
            float v0 = fmaxf(e0.x + e0.y + B1A[o], 0.f);
            float v1 = fmaxf(e1.x + e1.y + B1A[o], 0.f);
            if (o & 1) { ap0[o >> 1] = pk2(pr0, v0); ap1[o >> 1] = pk2(pr1, v1); }
            else       { pr0 = v0; pr1 = v1; }
        }
        MV_ROWS(W2A, B2A, ap0, ap1, false, U0, U1);
    }
    __syncthreads();

    // ============ layer B ============
    {
        ull ap0[16], ap1[16];
        {
            ull hp0[16], hp1[16];
            gather_relu((const char*)sm.U, off0, hp0);
            gather_relu((const char*)sm.U, off1, hp1);
            MV_REG(W1B, B1B, hp0, hp1, true, ap0, ap1);
        }
        __syncthreads();                 // all gathers done; U writable
        MV_ROWS(W2B, B2B, ap0, ap1, false, U0, U1);
    }
    __syncthreads();

    // ============ layer C ============
    {
        ull ap0[16], ap1[16];
        {
            ull hp0[16], hp1[16];
            gather_relu((const char*)sm.U, off0, hp0);
            gather_relu((const char*)sm.U, off1, hp1);
            MV_REG(W1C, B1C, hp0, hp1, true, ap0, ap1);
        }
        __syncthreads();
        MV_ROWS(W2C, B2C, ap0, ap1, false, U0, U1);
    }
    __syncthreads();

    // ===== pool: self-loops => g[c] = relu(max_n u3[n][c]) =====
    {
        int c = t & 31, s = t >> 5;
        const float* col = sm.U + c;
        float m = -FINF;
#pragma unroll 4
        for (int i = 0; i < 64; i++)
            m = fmaxf(m, col[(s * 64 + i) * ROWF]);
        sm.red[s * 32 + c] = m;
    }
    __syncthreads();

    if (wid == 0) {
        float m = sm.red[lane];
#pragma unroll
        for (int s = 1; s < 8; s++) m = fmaxf(m, sm.red[s * 32 + lane]);
        float g = fmaxf(m, 0.f);
#pragma unroll
        for (int od = 0; od < 6; od++) {
            float pr = WR[od * 32 + lane] * g;
#pragma unroll
            for (int o2 = 16; o2 > 0; o2 >>= 1)
                pr += __shfl_xor_sync(0xffffffffu, pr, o2);
            if (lane == 0) out[b * 6 + od] = pr + BR[od];
        }
    }
}

extern "C" void kernel_launch(void* const* d_in, const int* in_sizes, int n_in,
                              void* d_out, int out_size)
{
    const float* x   = (const float*)d_in[0];
    const float* pos = (const float*)d_in[1];
    float* out = (float*)d_out;

    pack_weights<<<(NPACK + 255) / 256, 256>>>(
        (const float*)d_in[3],  (const float*)d_in[4],
        (const float*)d_in[5],  (const float*)d_in[6],
        (const float*)d_in[7],  (const float*)d_in[8],
        (const float*)d_in[9],  (const float*)d_in[10],
        (const float*)d_in[11], (const float*)d_in[12],
        (const float*)d_in[13], (const float*)d_in[14],
        (const float*)d_in[15], (const float*)d_in[16]);

    void* packp = nullptr;
    cudaGetSymbolAddress(&packp, g_pack);
    cudaMemcpyToSymbolAsync(cALL, packp, NPACK * sizeof(float), 0,
                            cudaMemcpyDeviceToDevice, 0);

    cudaFuncSetAttribute(knn_kernel,
                         cudaFuncAttributeMaxDynamicSharedMemorySize, (int)sizeof(SmemK));
    knn_kernel<<<NGRAPH * 2, 256, sizeof(SmemK)>>>(pos);

    cudaFuncSetAttribute(gcn_layers_kernel,
                         cudaFuncAttributeMaxDynamicSharedMemorySize, (int)sizeof(SmemL));
    gcn_layers_kernel<<<NGRAPH, 256, sizeof(SmemL)>>>(x, pos, out);
}

// round 14
// speedup vs baseline: 1.7761x; 1.7761x over previous
#include <cuda_runtime.h>

#define NGRAPH 256
#define M      512
#define KNN    6
#define C      32
#define FINF   3.402823466e38f
#define ROWF   36            // padded U row (floats): 144B, 16B aligned
#define ROWB   144
#define P1N    128           // KNN phase-1 sample size
#define CAP    96            // per-thread u16 candidate buffer capacity
#define NPACK  5640          // packed weights (floats)

typedef unsigned long long ull;

__device__ float g_A[NGRAPH * M * C];
__device__ int   g_idxT[NGRAPH * KNN * M];   // [graph][k][node], byte offsets (idx*ROWB)
__device__ __align__(16) float g_pack[NPACK];

// packed-weight float offsets
#define O_W1A 0
#define O_B1A 128
#define O_W2A 160
#define O_B2A 1184
#define O_W1B 1216
#define O_B1B 2240
#define O_W2B 2272
#define O_B2B 3296
#define O_W1C 3328
#define O_B1C 4352
#define O_W2C 4384
#define O_B2C 5408
#define O_WR  5440
#define O_BR  5632

// single consolidated constant block (separate LDC port, parallel to L1 pipe)
__constant__ __align__(16) float cALL[NPACK];
#define W1A ((const ulonglong2*)(cALL + O_W1A))
#define W2A ((const ulonglong2*)(cALL + O_W2A))
#define W1B ((const ulonglong2*)(cALL + O_W1B))
#define W2B ((const ulonglong2*)(cALL + O_W2B))
#define W1C ((const ulonglong2*)(cALL + O_W1C))
#define W2C ((const ulonglong2*)(cALL + O_W2C))
#define B1A (cALL + O_B1A)
#define B2A (cALL + O_B2A)
#define B1B (cALL + O_B1B)
#define B2B (cALL + O_B2B)
#define B1C (cALL + O_B1C)
#define B2C (cALL + O_B2C)
#define WR  (cALL + O_WR)
#define BR  (cALL + O_BR)

static __device__ __forceinline__ ull pk2(float lo, float hi) {
    ull d; asm("mov.b64 %0, {%1, %2};" : "=l"(d) : "f"(lo), "f"(hi)); return d;
}
static __device__ __forceinline__ float2 upk2(ull v) {
    float2 r; asm("mov.b64 {%0, %1}, %2;" : "=f"(r.x), "=f"(r.y) : "l"(v)); return r;
}
static __device__ __forceinline__ ull ffma2(ull a, ull b, ull c) {
    ull d; asm("fma.rn.f32x2 %0, %1, %2, %3;" : "=l"(d) : "l"(a), "l"(b), "l"(c)); return d;
}
static __device__ __forceinline__ float4 fmax4(float4 a, float4 b) {
    return make_float4(fmaxf(a.x, b.x), fmaxf(a.y, b.y),
                       fmaxf(a.z, b.z), fmaxf(a.w, b.w));
}
static __device__ __forceinline__ void sts16_if(unsigned addr, unsigned short v, int pred) {
    asm volatile("{\n\t.reg .pred p;\n\tsetp.ne.s32 p, %2, 0;\n\t"
                 "@p st.shared.u16 [%0], %1;\n\t}"
                 :: "r"(addr), "h"(v), "r"(pred));
}
static __device__ __forceinline__ float d2f(float4 a, float4 j) {
    float dot = fmaf(a.x, j.x, fmaf(a.y, j.y, a.z * j.z));
    return fmaf(-2.0f, dot, a.w + j.w);       // exact reference formula
}

__device__ __forceinline__ void kins(float (&bd)[KNN], int (&bi)[KNN],
                                     float xd, int xi)
{
#pragma unroll
    for (int k = 0; k < KNN; k++) {
        bool  p  = xd < bd[k];                // strict: stable (ties keep earlier j)
        float td = bd[k];
        int   ti = bi[k];
        bd[k] = p ? xd : bd[k];
        bi[k] = p ? xi : bi[k];
        xd    = p ? td : xd;
        xi    = p ? ti : xi;
    }
}

// ============================================================================
// Kernel 0: parallel weight pack (one float per thread) — verified 4.1us
// ============================================================================
__global__ void pack_weights(
    const float* __restrict__ W1a, const float* __restrict__ b1a,
    const float* __restrict__ W2a, const float* __restrict__ b2a,
    const float* __restrict__ W1b, const float* __restrict__ b1b,
    const float* __restrict__ W2b, const float* __restrict__ b2b,
    const float* __restrict__ W1c, const float* __restrict__ b1c,
    const float* __restrict__ W2c, const float* __restrict__ b2c,
    const float* __restrict__ Wr,  const float* __restrict__ br)
{
    int i = blockIdx.x * blockDim.x + threadIdx.x;
    if (i >= NPACK) return;
    float v = 0.f;
    if      (i < O_B1A) v = W1a[i - O_W1A];
    else if (i < O_W2A) v = b1a[i - O_B1A];
    else if (i < O_B2A) v = W2a[i - O_W2A];
    else if (i < O_W1B) v = b2a[i - O_B2A];
    else if (i < O_B1B) v = W1b[i - O_W1B];
    else if (i < O_W2B) v = b1b[i - O_B1B];
    else if (i < O_B2B) v = W2b[i - O_W2B];
    else if (i < O_W1C) v = b2b[i - O_B2B];
    else if (i < O_B1C) v = W1c[i - O_W1C];
    else if (i < O_W2C) v = b1c[i - O_B1C];
    else if (i < O_B2C) v = W2c[i - O_W2C];
    else if (i < O_WR)  v = b2c[i - O_B2C];
    else if (i < O_BR)  v = Wr[i - O_WR];
    else if (i < O_BR + 6) v = br[i - O_BR];
    g_pack[i] = v;
}

// ============================================================================
// Kernel 1: 3-phase KNN. 2 blocks/graph, 256 threads, 1 node/thread.
// (verified component of the 119.9us config)
// ============================================================================
struct __align__(16) SmemK {
    float4 pos4s[M];                  //  8 KB
    unsigned short buf[256 * CAP];    // 48 KB
};

__global__ void __launch_bounds__(256, 4) knn_kernel(const float* __restrict__ pos)
{
    extern __shared__ char smem_raw[];
    SmemK& sk = *reinterpret_cast<SmemK*>(smem_raw);
    const int b    = blockIdx.x >> 1;
    const int half = blockIdx.x & 1;
    const int t    = threadIdx.x;

#pragma unroll
    for (int i = 0; i < 2; i++) {
        int nn = i * 256 + t;
        const float* p = pos + ((size_t)b * M + nn) * 3;
        float px = p[0], py = p[1], pz = p[2];
        sk.pos4s[nn] = make_float4(px, py, pz, px * px + py * py + pz * pz);
    }
    __syncthreads();

    const int n = half * 256 + t;
    const float4 pn = sk.pos4s[n];

    // ---- phase 1: branchless value-only top-6 over first P1N (exact d2) ----
    float v[KNN];
#pragma unroll
    for (int k = 0; k < KNN; k++) v[k] = FINF;
#pragma unroll 2
    for (int j = 0; j < P1N; j++) {
        float a = d2f(pn, sk.pos4s[j]);
#pragma unroll
        for (int k = 0; k < KNN; k++) {
            float lo = fminf(a, v[k]); a = fmaxf(a, v[k]); v[k] = lo;
        }
    }
    const float taup = (v[KNN - 1] - pn.w) + 1e-4f;   // cheap-metric threshold + margin

    // ---- phase 2: full scan, predicated append ----
    unsigned short* mybuf = sk.buf + t * CAP;
    unsigned bufaddr = (unsigned)__cvta_generic_to_shared(mybuf);
    int cnt = 0;
#pragma unroll 1
    for (int j0 = 0; j0 < M; j0 += 4) {
        float e[4];
#pragma unroll
        for (int u = 0; u < 4; u++) {
            float4 pj = sk.pos4s[j0 + u];
            float dot = fmaf(pn.x, pj.x, fmaf(pn.y, pj.y, pn.z * pj.z));
            e[u] = fmaf(-2.0f, dot, pj.w);
        }
        int basec = cnt < (CAP - 4) ? cnt : (CAP - 4);
#pragma unroll
        for (int u = 0; u < 4; u++) {
            int p = e[u] <= taup;
            sts16_if(bufaddr + 2u * (unsigned)basec, (unsigned short)(j0 + u), p);
            basec += p;
            cnt   += p;
        }
    }
    asm volatile("" ::: "memory");

    // ---- phase 3: exact stable top-6 ----
    float bd[KNN];
    int   bi[KNN];
#pragma unroll
    for (int k = 0; k < KNN; k++) { bd[k] = FINF; bi[k] = 0; }

    if (cnt <= CAP) {
        for (int i = 0; i < cnt; i++) {
            int j = mybuf[i];
            float d = d2f(pn, sk.pos4s[j]);
            if (d < bd[KNN - 1]) kins(bd, bi, d, j);
        }
    } else {
        for (int j = 0; j < M; j++) {       // rare exact fallback
            float d = d2f(pn, sk.pos4s[j]);
            if (d < bd[KNN - 1]) kins(bd, bi, d, j);
        }
    }

    int* dst = g_idxT + (size_t)b * (KNN * M);
#pragma unroll
    for (int k = 0; k < KNN; k++)
        dst[k * M + n] = bi[k] * ROWB;
}

// ============================================================================
// Kernel 2: fused layers, 2 nodes/thread, constant weights, g_A round-trip.
// (verified 75us component of the 119.9us config — balanced LDC/L1/regs)
// ============================================================================
struct __align__(16) SmemL {
    float U[M * ROWF];   // 73728 B
    float red[256];      //  1024 B
};                       // ~75KB -> 2 CTAs/SM

static __device__ __forceinline__ void gather_relu(const char* __restrict__ Up,
                                                   const int* __restrict__ off,
                                                   ull* __restrict__ hp)
{
#pragma unroll
    for (int c4 = 0; c4 < 8; c4++) {
        int byo = c4 * 16;
        float4 m = *(const float4*)(Up + off[0] + byo);
        m = fmax4(m, *(const float4*)(Up + off[1] + byo));
        m = fmax4(m, *(const float4*)(Up + off[2] + byo));
        m = fmax4(m, *(const float4*)(Up + off[3] + byo));
        m = fmax4(m, *(const float4*)(Up + off[4] + byo));
        m = fmax4(m, *(const float4*)(Up + off[5] + byo));
        m.x = fmaxf(m.x, 0.f); m.y = fmaxf(m.y, 0.f);
        m.z = fmaxf(m.z, 0.f); m.w = fmaxf(m.w, 0.f);
        hp[2 * c4]     = pk2(m.x, m.y);
        hp[2 * c4 + 1] = pk2(m.z, m.w);
    }
}

// dual-node 32x32 matvec rows with 4-wide store packing
#define MV_ROWS(W, BIAS, P0, P1, RELU, D0, D1)                                  \
    {                                                                           \
        ull s0lo = 0, s0hi = 0, s1lo = 0, s1hi = 0;                             \
        _Pragma("unroll")                                                       \
        for (int o = 0; o < 32; o++) {                                          \
            ull a0 = 0, a1 = 0, b0 = 0, b1 = 0;                                 \
            _Pragma("unroll")                                                   \
            for (int q = 0; q < 8; q++) {                                       \
                ulonglong2 w = (W)[o * 8 + q];                                  \
                a0 = ffma2(w.x, (P0)[2 * q],     a0);                           \
                a1 = ffma2(w.y, (P0)[2 * q + 1], a1);                           \
                b0 = ffma2(w.x, (P1)[2 * q],     b0);                           \
                b1 = ffma2(w.y, (P1)[2 * q + 1], b1);                           \
            }                                                                   \
            float2 e0 = upk2(a0), e1 = upk2(a1);                                \
            float2 f0 = upk2(b0), f1 = upk2(b1);                                \
            float v0 = (e0.x + e0.y) + (e1.x + e1.y) + (BIAS)[o];               \
            float v1 = (f0.x + f0.y) + (f1.x + f1.y) + (BIAS)[o];               \
            if (RELU) { v0 = fmaxf(v0, 0.f); v1 = fmaxf(v1, 0.f); }             \
            switch (o & 3) {                                                    \
              case 0: s0lo = pk2(v0, 0.f); s1lo = pk2(v1, 0.f); break;          \
              case 1: { float2 c0 = upk2(s0lo); s0lo = pk2(c0.x, v0);           \
                        float2 c1 = upk2(s1lo); s1lo = pk2(c1.x, v1); } break;  \
              case 2: s0hi = pk2(v0, 0.f); s1hi = pk2(v1, 0.f); break;          \
              default: {                                                        \
                float2 c0 = upk2(s0hi); s0hi = pk2(c0.x, v0);                   \
                float2 c1 = upk2(s1hi); s1hi = pk2(c1.x, v1);                   \
                *(ulonglong2*)((D0) + o - 3) = make_ulonglong2(s0lo, s0hi);     \
                *(ulonglong2*)((D1) + o - 3) = make_ulonglong2(s1lo, s1hi);     \
              } break;                                                          \
            }                                                                   \
        }                                                                       \
    }

__global__ void __launch_bounds__(256, 2) gcn_layers_kernel(
    const float* __restrict__ x, const float* __restrict__ pos,
    float* __restrict__ out)
{
    extern __shared__ char smem_raw[];
    SmemL& sm = *reinterpret_cast<SmemL*>(smem_raw);

    const int b    = blockIdx.x;
    const int t    = threadIdx.x;
    const int lane = t & 31;
    const int wid  = t >> 5;
    const int n0   = t;
    const int n1   = t + 256;

    float* __restrict__ Ag = g_A + (size_t)b * M * C;

    int off0[KNN], off1[KNN];
    {
        const int* it = g_idxT + (size_t)b * (KNN * M);
#pragma unroll
        for (int k = 0; k < KNN; k++) {
            off0[k] = it[k * M + n0];
            off1[k] = it[k * M + n1];
        }
    }

    // ============ layer A: all-register, straight to U ============
    {
        float x0 = x[(size_t)b * M + n0];
        float x1 = x[(size_t)b * M + n1];
        const float* p0 = pos + ((size_t)b * M + n0) * 3;
        const float* p1 = pos + ((size_t)b * M + n1) * 3;
        ull i0a = pk2(x0, p0[0]), i0b = pk2(p0[1], p0[2]);
        ull i1a = pk2(x1, p1[0]), i1b = pk2(p1[1], p1[2]);

        ull ap0[16], ap1[16];
        float pr0 = 0.f, pr1 = 0.f;
#pragma unroll
        for (int o = 0; o < 32; o++) {
            ulonglong2 w = W1A[o];
            float2 e0 = upk2(ffma2(w.x, i0a, ffma2(w.y, i0b, 0ull)));
            float2 e1 = upk2(ffma2(w.x, i1a, ffma2(w.y, i1b, 0ull)));
            float v0 = fmaxf(e0.x + e0.y + B1A[o], 0.f);
            float v1 = fmaxf(e1.x + e1.y + B1A[o], 0.f);
            if (o & 1) { ap0[o >> 1] = pk2(pr0, v0); ap1[o >> 1] = pk2(pr1, v1); }
            else       { pr0 = v0; pr1 = v1; }
        }
        float* U0 = sm.U + n0 * ROWF;
        float* U1 = sm.U + n1 * ROWF;
        MV_ROWS(W2A, B2A, ap0, ap1, false, U0, U1);
    }
    __syncthreads();

    {   // layer B ph1: gather + mv1 -> Ag
        ull hp0[16], hp1[16];
        gather_relu((const char*)sm.U, off0, hp0);
        gather_relu((const char*)sm.U, off1, hp1);
        float* A0 = Ag + n0 * C;
        float* A1 = Ag + n1 * C;
        MV_ROWS(W1B, B1B, hp0, hp1, true, A0, A1);
    }
    __syncthreads();
    {   // layer B ph2: Ag -> U
        ull ap0[16], ap1[16];
        const ulonglong2* r0 = (const ulonglong2*)(Ag + n0 * C);
        const ulonglong2* r1 = (const ulonglong2*)(Ag + n1 * C);
#pragma unroll
        for (int q = 0; q < 8; q++) {
            ulonglong2 v0 = r0[q]; ap0[2 * q] = v0.x; ap0[2 * q + 1] = v0.y;
            ulonglong2 v1 = r1[q]; ap1[2 * q] = v1.x; ap1[2 * q + 1] = v1.y;
        }
        float* U0 = sm.U + n0 * ROWF;
        float* U1 = sm.U + n1 * ROWF;
        MV_ROWS(W2B, B2B, ap0, ap1, false, U0, U1);
    }
    __syncthreads();
    {   // layer C ph1
        ull hp0[16], hp1[16];
        gather_relu((const char*)sm.U, off0, hp0);
        gather_relu((const char*)sm.U, off1, hp1);
        float* A0 = Ag + n0 * C;
        float* A1 = Ag + n1 * C;
        MV_ROWS(W1C, B1C, hp0, hp1, true, A0, A1);
    }
    __syncthreads();
    {   // layer C ph2
        ull ap0[16], ap1[16];
        const ulonglong2* r0 = (const ulonglong2*)(Ag + n0 * C);
        const ulonglong2* r1 = (const ulonglong2*)(Ag + n1 * C);
#pragma unroll
        for (int q = 0; q < 8; q++) {
            ulonglong2 v0 = r0[q]; ap0[2 * q] = v0.x; ap0[2 * q + 1] = v0.y;
            ulonglong2 v1 = r1[q]; ap1[2 * q] = v1.x; ap1[2 * q + 1] = v1.y;
        }
        float* U0 = sm.U + n0 * ROWF;
        float* U1 = sm.U + n1 * ROWF;
        MV_ROWS(W2C, B2C, ap0, ap1, false, U0, U1);
    }
    __syncthreads();

    // ===== pool: self-loops => g[c] = relu(max_n u3[n][c]) =====
    {
        int c = t & 31, s = t >> 5;
        const float* col = sm.U + c;
        float m = -FINF;
#pragma unroll 4
        for (int i = 0; i < 64; i++)
            m = fmaxf(m, col[(s * 64 + i) * ROWF]);
        sm.red[s * 32 + c] = m;
    }
    __syncthreads();

    if (wid == 0) {
        float m = sm.red[lane];
#pragma unroll
        for (int s = 1; s < 8; s++) m = fmaxf(m, sm.red[s * 32 + lane]);
        float g = fmaxf(m, 0.f);
#pragma unroll
        for (int od = 0; od < 6; od++) {
            float pr = WR[od * 32 + lane] * g;
#pragma unroll
            for (int o2 = 16; o2 > 0; o2 >>= 1)
                pr += __shfl_xor_sync(0xffffffffu, pr, o2);
            if (lane == 0) out[b * 6 + od] = pr + BR[od];
        }
    }
}

extern "C" void kernel_launch(void* const* d_in, const int* in_sizes, int n_in,
                              void* d_out, int out_size)
{
    const float* x   = (const float*)d_in[0];
    const float* pos = (const float*)d_in[1];
    float* out = (float*)d_out;

    pack_weights<<<(NPACK + 255) / 256, 256>>>(
        (const float*)d_in[3],  (const float*)d_in[4],
        (const float*)d_in[5],  (const float*)d_in[6],
        (const float*)d_in[7],  (const float*)d_in[8],
        (const float*)d_in[9],  (const float*)d_in[10],
        (const float*)d_in[11], (const float*)d_in[12],
        (const float*)d_in[13], (const float*)d_in[14],
        (const float*)d_in[15], (const float*)d_in[16]);

    void* packp = nullptr;
    cudaGetSymbolAddress(&packp, g_pack);
    cudaMemcpyToSymbolAsync(cALL, packp, NPACK * sizeof(float), 0,
                            cudaMemcpyDeviceToDevice, 0);

    cudaFuncSetAttribute(knn_kernel,
                         cudaFuncAttributeMaxDynamicSharedMemorySize, (int)sizeof(SmemK));
    knn_kernel<<<NGRAPH * 2, 256, sizeof(SmemK)>>>(pos);

    cudaFuncSetAttribute(gcn_layers_kernel,
                         cudaFuncAttributeMaxDynamicSharedMemorySize, (int)sizeof(SmemL));
    gcn_layers_kernel<<<NGRAPH, 256, sizeof(SmemL)>>>(x, pos, out);
}

// round 15
// speedup vs baseline: 1.8086x; 1.0183x over previous
#include <cuda_runtime.h>

#define NGRAPH 256
#define M      512
#define KNN    6
#define C      32
#define FINF   3.402823466e38f
#define ROWF   36            // padded U row (floats): 144B, 16B aligned
#define ROWB   144
#define P1N    128           // KNN phase-1 sample size
#define CAP    96            // per-thread u16 candidate buffer capacity
#define NPACK  5640          // packed weights (floats)

typedef unsigned long long ull;

__device__ float g_A[NGRAPH * M * C];
__device__ int   g_idxT[NGRAPH * KNN * M];   // [graph][k][node], byte offsets (idx*ROWB)
__device__ __align__(16) float g_pack[NPACK];

// packed-weight float offsets
#define O_W1A 0
#define O_B1A 128
#define O_W2A 160
#define O_B2A 1184
#define O_W1B 1216
#define O_B1B 2240
#define O_W2B 2272
#define O_B2B 3296
#define O_W1C 3328
#define O_B1C 4352
#define O_W2C 4384
#define O_B2C 5408
#define O_WR  5440
#define O_BR  5632

// single consolidated constant block (separate LDC port, parallel to L1 pipe)
__constant__ __align__(16) float cALL[NPACK];
#define W1A ((const ulonglong2*)(cALL + O_W1A))
#define W2A ((const ulonglong2*)(cALL + O_W2A))
#define W1B ((const ulonglong2*)(cALL + O_W1B))
#define W2B ((const ulonglong2*)(cALL + O_W2B))
#define W1C ((const ulonglong2*)(cALL + O_W1C))
#define W2C ((const ulonglong2*)(cALL + O_W2C))
#define B1A (cALL + O_B1A)
#define B2A (cALL + O_B2A)
#define B1B (cALL + O_B1B)
#define B2B (cALL + O_B2B)
#define B1C (cALL + O_B1C)
#define B2C (cALL + O_B2C)
#define WR  (cALL + O_WR)
#define BR  (cALL + O_BR)

static __device__ __forceinline__ ull pk2(float lo, float hi) {
    ull d; asm("mov.b64 %0, {%1, %2};" : "=l"(d) : "f"(lo), "f"(hi)); return d;
}
static __device__ __forceinline__ float2 upk2(ull v) {
    float2 r; asm("mov.b64 {%0, %1}, %2;" : "=f"(r.x), "=f"(r.y) : "l"(v)); return r;
}
static __device__ __forceinline__ ull ffma2(ull a, ull b, ull c) {
    ull d; asm("fma.rn.f32x2 %0, %1, %2, %3;" : "=l"(d) : "l"(a), "l"(b), "l"(c)); return d;
}
static __device__ __forceinline__ float4 fmax4(float4 a, float4 b) {
    return make_float4(fmaxf(a.x, b.x), fmaxf(a.y, b.y),
                       fmaxf(a.z, b.z), fmaxf(a.w, b.w));
}
static __device__ __forceinline__ void sts16_if(unsigned addr, unsigned short v, int pred) {
    asm volatile("{\n\t.reg .pred p;\n\tsetp.ne.s32 p, %2, 0;\n\t"
                 "@p st.shared.u16 [%0], %1;\n\t}"
                 :: "r"(addr), "h"(v), "r"(pred));
}
static __device__ __forceinline__ float d2f(float4 a, float4 j) {
    float dot = fmaf(a.x, j.x, fmaf(a.y, j.y, a.z * j.z));
    return fmaf(-2.0f, dot, a.w + j.w);       // exact reference formula
}

__device__ __forceinline__ void kins(float (&bd)[KNN], int (&bi)[KNN],
                                     float xd, int xi)
{
#pragma unroll
    for (int k = 0; k < KNN; k++) {
        bool  p  = xd < bd[k];                // strict: stable (ties keep earlier j)
        float td = bd[k];
        int   ti = bi[k];
        bd[k] = p ? xd : bd[k];
        bi[k] = p ? xi : bi[k];
        xd    = p ? td : xd;
        xi    = p ? ti : xi;
    }
}

// ============================================================================
// Kernel 0: parallel weight pack (verified 4.1us)
// ============================================================================
__global__ void pack_weights(
    const float* __restrict__ W1a, const float* __restrict__ b1a,
    const float* __restrict__ W2a, const float* __restrict__ b2a,
    const float* __restrict__ W1b, const float* __restrict__ b1b,
    const float* __restrict__ W2b, const float* __restrict__ b2b,
    const float* __restrict__ W1c, const float* __restrict__ b1c,
    const float* __restrict__ W2c, const float* __restrict__ b2c,
    const float* __restrict__ Wr,  const float* __restrict__ br)
{
    int i = blockIdx.x * blockDim.x + threadIdx.x;
    if (i >= NPACK) return;
    float v = 0.f;
    if      (i < O_B1A) v = W1a[i - O_W1A];
    else if (i < O_W2A) v = b1a[i - O_B1A];
    else if (i < O_B2A) v = W2a[i - O_W2A];
    else if (i < O_W1B) v = b2a[i - O_B2A];
    else if (i < O_B1B) v = W1b[i - O_W1B];
    else if (i < O_W2B) v = b1b[i - O_B1B];
    else if (i < O_B2B) v = W2b[i - O_W2B];
    else if (i < O_W1C) v = b2b[i - O_B2B];
    else if (i < O_B1C) v = W1c[i - O_W1C];
    else if (i < O_W2C) v = b1c[i - O_B1C];
    else if (i < O_B2C) v = W2c[i - O_W2C];
    else if (i < O_WR)  v = b2c[i - O_B2C];
    else if (i < O_BR)  v = Wr[i - O_WR];
    else if (i < O_BR + 6) v = br[i - O_BR];
    g_pack[i] = v;
}

// ============================================================================
// Kernel 1: 3-phase KNN. 2 blocks/graph, 256 threads, 1 node/thread. (proven)
// ============================================================================
struct __align__(16) SmemK {
    float4 pos4s[M];                  //  8 KB
    unsigned short buf[256 * CAP];    // 48 KB
};

__global__ void __launch_bounds__(256, 4) knn_kernel(const float* __restrict__ pos)
{
    extern __shared__ char smem_raw[];
    SmemK& sk = *reinterpret_cast<SmemK*>(smem_raw);
    const int b    = blockIdx.x >> 1;
    const int half = blockIdx.x & 1;
    const int t    = threadIdx.x;

#pragma unroll
    for (int i = 0; i < 2; i++) {
        int nn = i * 256 + t;
        const float* p = pos + ((size_t)b * M + nn) * 3;
        float px = p[0], py = p[1], pz = p[2];
        sk.pos4s[nn] = make_float4(px, py, pz, px * px + py * py + pz * pz);
    }
    __syncthreads();

    const int n = half * 256 + t;
    const float4 pn = sk.pos4s[n];

    // ---- phase 1: branchless value-only top-6 over first P1N (exact d2) ----
    float v[KNN];
#pragma unroll
    for (int k = 0; k < KNN; k++) v[k] = FINF;
#pragma unroll 2
    for (int j = 0; j < P1N; j++) {
        float a = d2f(pn, sk.pos4s[j]);
#pragma unroll
        for (int k = 0; k < KNN; k++) {
            float lo = fminf(a, v[k]); a = fmaxf(a, v[k]); v[k] = lo;
        }
    }
    const float taup = (v[KNN - 1] - pn.w) + 1e-4f;

    // ---- phase 2: full scan, predicated append ----
    unsigned short* mybuf = sk.buf + t * CAP;
    unsigned bufaddr = (unsigned)__cvta_generic_to_shared(mybuf);
    int cnt = 0;
#pragma unroll 1
    for (int j0 = 0; j0 < M; j0 += 4) {
        float e[4];
#pragma unroll
        for (int u = 0; u < 4; u++) {
            float4 pj = sk.pos4s[j0 + u];
            float dot = fmaf(pn.x, pj.x, fmaf(pn.y, pj.y, pn.z * pj.z));
            e[u] = fmaf(-2.0f, dot, pj.w);
        }
        int basec = cnt < (CAP - 4) ? cnt : (CAP - 4);
#pragma unroll
        for (int u = 0; u < 4; u++) {
            int p = e[u] <= taup;
            sts16_if(bufaddr + 2u * (unsigned)basec, (unsigned short)(j0 + u), p);
            basec += p;
            cnt   += p;
        }
    }
    asm volatile("" ::: "memory");

    // ---- phase 3: exact stable top-6 ----
    float bd[KNN];
    int   bi[KNN];
#pragma unroll
    for (int k = 0; k < KNN; k++) { bd[k] = FINF; bi[k] = 0; }

    if (cnt <= CAP) {
        for (int i = 0; i < cnt; i++) {
            int j = mybuf[i];
            float d = d2f(pn, sk.pos4s[j]);
            if (d < bd[KNN - 1]) kins(bd, bi, d, j);
        }
    } else {
        for (int j = 0; j < M; j++) {       // rare exact fallback
            float d = d2f(pn, sk.pos4s[j]);
            if (d < bd[KNN - 1]) kins(bd, bi, d, j);
        }
    }

    int* dst = g_idxT + (size_t)b * (KNN * M);
#pragma unroll
    for (int k = 0; k < KNN; k++)
        dst[k * M + n] = bi[k] * ROWB;
}

// ============================================================================
// Kernel 2: fused layers — 512 threads, 1 node/thread, 2 CTAs/SM
// (8 warps/SMSP for latency hiding; constant weights; g_A round-trip)
// ============================================================================
struct __align__(16) SmemL {
    float U[M * ROWF];   // 73728 B
    float red[512];      //  2048 B
};                       // 75776 B -> 2 CTAs/SM (151.5KB of 228KB)

static __device__ __forceinline__ void gather_relu(const char* __restrict__ Up,
                                                   const int* __restrict__ off,
                                                   ull* __restrict__ hp)
{
#pragma unroll
    for (int c4 = 0; c4 < 8; c4++) {
        int byo = c4 * 16;
        float4 m = *(const float4*)(Up + off[0] + byo);
        m = fmax4(m, *(const float4*)(Up + off[1] + byo));
        m = fmax4(m, *(const float4*)(Up + off[2] + byo));
        m = fmax4(m, *(const float4*)(Up + off[3] + byo));
        m = fmax4(m, *(const float4*)(Up + off[4] + byo));
        m = fmax4(m, *(const float4*)(Up + off[5] + byo));
        m.x = fmaxf(m.x, 0.f); m.y = fmaxf(m.y, 0.f);
        m.z = fmaxf(m.z, 0.f); m.w = fmaxf(m.w, 0.f);
        hp[2 * c4]     = pk2(m.x, m.y);
        hp[2 * c4 + 1] = pk2(m.z, m.w);
    }
}

// single-node 32x32 matvec rows with 4-wide store packing
#define MV_ROWS1(W, BIAS, P, RELU, D)                                           \
    {                                                                           \
        ull slo = 0, shi = 0;                                                   \
        _Pragma("unroll")                                                       \
        for (int o = 0; o < 32; o++) {                                          \
            ull a0 = 0, a1 = 0;                                                 \
            _Pragma("unroll")                                                   \
            for (int q = 0; q < 8; q++) {                                       \
                ulonglong2 w = (W)[o * 8 + q];                                  \
                a0 = ffma2(w.x, (P)[2 * q],     a0);                            \
                a1 = ffma2(w.y, (P)[2 * q + 1], a1);                            \
            }                                                                   \
            float2 e0 = upk2(a0), e1 = upk2(a1);                                \
            float v = (e0.x + e0.y) + (e1.x + e1.y) + (BIAS)[o];                \
            if (RELU) v = fmaxf(v, 0.f);                                        \
            switch (o & 3) {                                                    \
              case 0: slo = pk2(v, 0.f); break;                                 \
              case 1: { float2 c0 = upk2(slo); slo = pk2(c0.x, v); } break;     \
              case 2: shi = pk2(v, 0.f); break;                                 \
              default: {                                                        \
                float2 c0 = upk2(shi); shi = pk2(c0.x, v);                      \
                *(ulonglong2*)((D) + o - 3) = make_ulonglong2(slo, shi);        \
              } break;                                                          \
            }                                                                   \
        }                                                                       \
    }

__global__ void __launch_bounds__(512, 2) gcn_layers_kernel(
    const float* __restrict__ x, const float* __restrict__ pos,
    float* __restrict__ out)
{
    extern __shared__ char smem_raw[];
    SmemL& sm = *reinterpret_cast<SmemL*>(smem_raw);

    const int b    = blockIdx.x;
    const int t    = threadIdx.x;
    const int lane = t & 31;
    const int wid  = t >> 5;
    const int n    = t;                    // own node

    float* __restrict__ Ag = g_A + (size_t)b * M * C;
    float* Urow = sm.U + n * ROWF;
    float* Arow = Ag + n * C;

    int off[KNN];
    {
        const int* it = g_idxT + (size_t)b * (KNN * M) + n;
#pragma unroll
        for (int k = 0; k < KNN; k++) off[k] = it[k * M];
    }

    // ============ layer A: all-register, straight to U ============
    {
        float xv = x[(size_t)b * M + n];
        const float* p = pos + ((size_t)b * M + n) * 3;
        ull ia = pk2(xv, p[0]);
        ull ib = pk2(p[1], p[2]);

        ull ap[16];
        float pr = 0.f;
#pragma unroll
        for (int o = 0; o < 32; o++) {
            ulonglong2 w = W1A[o];
            float2 e = upk2(ffma2(w.x, ia, ffma2(w.y, ib, 0ull)));
            float v = fmaxf(e.x + e.y + B1A[o], 0.f);
            if (o & 1) ap[o >> 1] = pk2(pr, v); else pr = v;
        }
        MV_ROWS1(W2A, B2A, ap, false, Urow);
    }
    __syncthreads();

    {   // layer B ph1: gather + mv1 -> Ag
        ull hp[16];
        gather_relu((const char*)sm.U, off, hp);
        MV_ROWS1(W1B, B1B, hp, true, Arow);
    }
    __syncthreads();
    {   // layer B ph2: Ag -> U
        ull ap[16];
        const ulonglong2* r = (const ulonglong2*)Arow;
#pragma unroll
        for (int q = 0; q < 8; q++) {
            ulonglong2 v = r[q]; ap[2 * q] = v.x; ap[2 * q + 1] = v.y;
        }
        MV_ROWS1(W2B, B2B, ap, false, Urow);
    }
    __syncthreads();
    {   // layer C ph1
        ull hp[16];
        gather_relu((const char*)sm.U, off, hp);
        MV_ROWS1(W1C, B1C, hp, true, Arow);
    }
    __syncthreads();
    {   // layer C ph2
        ull ap[16];
        const ulonglong2* r = (const ulonglong2*)Arow;
#pragma unroll
        for (int q = 0; q < 8; q++) {
            ulonglong2 v = r[q]; ap[2 * q] = v.x; ap[2 * q + 1] = v.y;
        }
        MV_ROWS1(W2C, B2C, ap, false, Urow);
    }
    __syncthreads();

    // ===== pool: self-loops => g[c] = relu(max_n u3[n][c]) =====
    {
        int c = t & 31, s = t >> 5;        // 16 stripes x 32 rows
        const float* col = sm.U + c;
        float m = -FINF;
#pragma unroll 4
        for (int i = 0; i < 32; i++)
            m = fmaxf(m, col[(s * 32 + i) * ROWF]);
        sm.red[s * 32 + c] = m;
    }
    __syncthreads();

    if (wid == 0) {
        float m = sm.red[lane];
#pragma unroll
        for (int s = 1; s < 16; s++) m = fmaxf(m, sm.red[s * 32 + lane]);
        float g = fmaxf(m, 0.f);
#pragma unroll
        for (int od = 0; od < 6; od++) {
            float pr = WR[od * 32 + lane] * g;
#pragma unroll
            for (int o2 = 16; o2 > 0; o2 >>= 1)
                pr += __shfl_xor_sync(0xffffffffu, pr, o2);
            if (lane == 0) out[b * 6 + od] = pr + BR[od];
        }
    }
}

extern "C" void kernel_launch(void* const* d_in, const int* in_sizes, int n_in,
                              void* d_out, int out_size)
{
    const float* x   = (const float*)d_in[0];
    const float* pos = (const float*)d_in[1];
    float* out = (float*)d_out;

    pack_weights<<<(NPACK + 255) / 256, 256>>>(
        (const float*)d_in[3],  (const float*)d_in[4],
        (const float*)d_in[5],  (const float*)d_in[6],
        (const float*)d_in[7],  (const float*)d_in[8],
        (const float*)d_in[9],  (const float*)d_in[10],
        (const float*)d_in[11], (const float*)d_in[12],
        (const float*)d_in[13], (const float*)d_in[14],
        (const float*)d_in[15], (const float*)d_in[16]);

    void* packp = nullptr;
    cudaGetSymbolAddress(&packp, g_pack);
    cudaMemcpyToSymbolAsync(cALL, packp, NPACK * sizeof(float), 0,
                            cudaMemcpyDeviceToDevice, 0);

    cudaFuncSetAttribute(knn_kernel,
                         cudaFuncAttributeMaxDynamicSharedMemorySize, (int)sizeof(SmemK));
    knn_kernel<<<NGRAPH * 2, 256, sizeof(SmemK)>>>(pos);

    cudaFuncSetAttribute(gcn_layers_kernel,
                         cudaFuncAttributeMaxDynamicSharedMemorySize, (int)sizeof(SmemL));
    gcn_layers_kernel<<<NGRAPH, 512, sizeof(SmemL)>>>(x, pos, out);
}